// round 13
// baseline (speedup 1.0000x reference)
#include <cuda_runtime.h>
#include <cuda_bf16.h>
#include <stdint.h>
#include <math.h>

// ---------------------------------------------------------------------------
// InteractionPredictor e3nn-GNN forward.
// Msg passes: fused mma.sync bf16-split + TP + scatter (validated R12).
// Lig chain: SAME fused kernel structure, TP result kept in smem, Z computed
// in-block (no Wl materialization). Rec GEMM: fused Hr-contraction epilogue.
// ---------------------------------------------------------------------------
#define NMAX  16384
#define EIMAX 40960

__device__ __align__(16) float g_nodeA[NMAX * 40];
__device__ __align__(16) float g_nodeB[NMAX * 40];
__device__ __align__(16) float g_msgs [NMAX * 40];
__device__ __align__(16) float g_Hr[EIMAX * 64];
__device__ float g_rh[EIMAX * 3];
// packed weight fragments: PB[slot][(jt*4+ks)*32+lane] = {bh0,bh1,bl0,bl1}
__device__ __align__(16) uint4 g_PB[3][72 * 4 * 32];     // m0w1, m1w1, lw1
__device__ __align__(16) __nv_bfloat16 g_TWth[512 * 320];   // rec_w1 restructured
__device__ __align__(16) __nv_bfloat16 g_TWtl[512 * 320];
__device__ __align__(16) __nv_bfloat16 g_Hlh[EIMAX * 64];
__device__ __align__(16) __nv_bfloat16 g_Hll[EIMAX * 64];
__device__ __align__(16) __nv_bfloat16 g_Zh[(size_t)EIMAX * 320];
__device__ __align__(16) __nv_bfloat16 g_Zl[(size_t)EIMAX * 320];

#define ACT_NORM 1.6789717f
#define PW0_8    0.025515518153991443f   // sqrt(1/24)/8
#define PWREC_8  0.006987712429686843f   // sqrt(1/320)/8
#define INV_SQ3  0.57735026918962576f
#define SQ3F     1.7320508075688772f
#define DEMB_C   37.716086f

__device__ __forceinline__ float silu_act(float s) {
    return s / (1.f + expf(-s)) * ACT_NORM;
}
__device__ __forceinline__ void cpa16(unsigned int dst, const void* src) {
    asm volatile("cp.async.ca.shared.global [%0], [%1], 16;" :: "r"(dst), "l"(src));
}
__device__ __forceinline__ void cpa_commit() { asm volatile("cp.async.commit_group;"); }
__device__ __forceinline__ void cpa_wait0()  { asm volatile("cp.async.wait_group 0;"); }

__device__ __forceinline__ void mma16816(float d[4],
        unsigned a0, unsigned a1, unsigned a2, unsigned a3,
        unsigned b0, unsigned b1) {
    asm volatile(
        "mma.sync.aligned.m16n8k16.row.col.f32.bf16.bf16.f32 "
        "{%0,%1,%2,%3}, {%4,%5,%6,%7}, {%8,%9}, {%0,%1,%2,%3};"
        : "+f"(d[0]), "+f"(d[1]), "+f"(d[2]), "+f"(d[3])
        : "r"(a0), "r"(a1), "r"(a2), "r"(a3), "r"(b0), "r"(b1));
}
__device__ __forceinline__ unsigned lds32(unsigned addr) {
    unsigned v;
    asm volatile("ld.shared.b32 %0, [%1];" : "=r"(v) : "r"(addr));
    return v;
}
__device__ __forceinline__ unsigned pack_bf16x2(float a, float b) {
    __nv_bfloat162 v(__float2bfloat16(a), __float2bfloat16(b));
    return *(unsigned*)&v;
}

// ---------------------------------------------------------------------------
// Packed B image: entry (jt, ks, lane) -> 16B {bh0, bh1, bl0, bl1}.
// ---------------------------------------------------------------------------
__global__ void k_prepPB(const float* __restrict__ mw1, int which) {
    int idx = blockIdx.x * 256 + threadIdx.x;
    if (idx >= 72 * 4 * 32) return;
    int lane = idx & 31;
    int ks = (idx >> 5) & 3;
    int jt = idx >> 7;
    int j = jt * 8 + (lane >> 2);
    int k = ks * 16 + (lane & 3) * 2;
    float v00 = mw1[k * 576 + j],       v01 = mw1[(k + 1) * 576 + j];
    float v10 = mw1[(k + 8) * 576 + j], v11 = mw1[(k + 9) * 576 + j];
    float h00 = __bfloat162float(__float2bfloat16(v00));
    float h01 = __bfloat162float(__float2bfloat16(v01));
    float h10 = __bfloat162float(__float2bfloat16(v10));
    float h11 = __bfloat162float(__float2bfloat16(v11));
    uint4 o;
    o.x = pack_bf16x2(v00, v01);
    o.y = pack_bf16x2(v10, v11);
    o.z = pack_bf16x2(v00 - h00, v01 - h01);
    o.w = pack_bf16x2(v10 - h10, v11 - h11);
    g_PB[which][idx] = o;
}

__global__ void k_prepTW(const float* __restrict__ rw1) {
    int idx = blockIdx.x * 256 + threadIdx.x;
    if (idx >= 512 * 320) return;
    int j = idx / 320, p = idx - j * 320;
    int kk = j >> 3, w = j & 7;
    float v = rw1[kk * 2560 + p * 8 + w];
    __nv_bfloat16 hi = __float2bfloat16(v);
    g_TWth[idx] = hi;
    g_TWtl[idx] = __float2bfloat16(v - __bfloat162float(hi));
}

__global__ void k_zero(float* __restrict__ p, int n) {
    int idx = blockIdx.x * 256 + threadIdx.x;
    if (idx < n) p[idx] = 0.f;
}

// ---------------------------------------------------------------------------
// TP register accumulation (validated R9-R12).
// ---------------------------------------------------------------------------
__device__ __forceinline__ void tp_acc(int jb, const float d[4],
        float accS[2][4], float accG[2][2][3],
        const float* Fs, const float* Ds, const float rh[2][3], int le0) {
    int le1 = le0 + 8;
    if (jb < 256) {
        int u = jb >> 4, oh = (jb >> 3) & 1;
        float f0 = Fs[le0 * 41 + u];
        float f1 = Fs[le1 * 41 + u];
        accS[0][oh * 2 + 0] += f0 * d[0];
        accS[0][oh * 2 + 1] += f0 * d[1];
        accS[1][oh * 2 + 0] += f1 * d[2];
        accS[1][oh * 2 + 1] += f1 * d[3];
    } else if (jb < 384) {
        int u = (jb - 256) >> 4, oh = (jb >> 3) & 1;
        float f0 = Ds[le0 * 8 + u];
        float f1 = Ds[le1 * 8 + u];
        accS[0][oh * 2 + 0] += f0 * d[0];
        accS[0][oh * 2 + 1] += f0 * d[1];
        accS[1][oh * 2 + 0] += f1 * d[2];
        accS[1][oh * 2 + 1] += f1 * d[3];
    } else if (jb < 512) {
        int u = (jb - 384) >> 3;
        float f0 = SQ3F * Fs[le0 * 41 + u];
        float f1 = SQ3F * Fs[le1 * 41 + u];
        #pragma unroll
        for (int i = 0; i < 3; i++) {
            accG[0][0][i] += f0 * d[0] * rh[0][i];
            accG[0][1][i] += f0 * d[1] * rh[0][i];
            accG[1][0][i] += f1 * d[2] * rh[1][i];
            accG[1][1][i] += f1 * d[3] * rh[1][i];
        }
    } else {
        int u = (jb - 512) >> 3;
        #pragma unroll
        for (int i = 0; i < 3; i++) {
            float f0 = Fs[le0 * 41 + 16 + u * 3 + i];
            float f1 = Fs[le1 * 41 + 16 + u * 3 + i];
            accG[0][0][i] += f0 * d[0];
            accG[0][1][i] += f0 * d[1];
            accG[1][0][i] += f1 * d[2];
            accG[1][1][i] += f1 * d[3];
        }
    }
}

// Shared mma mainloop: A fragments (2 m-tiles) vs packed B; accumulate TP.
__device__ __forceinline__ void mma_tp_loop(
        const uint4* __restrict__ PB,
        const unsigned ah[2][4][4], const unsigned al[2][4][4],
        float accS[2][2][4], float accG[2][2][2][3],
        const float* Fs, const float* Ds, const float rh[2][2][3],
        int warp, int r0, int lane) {
    #pragma unroll 1
    for (int jt = 0; jt < 72; jt += 2) {
        const uint4* p0 = PB + (size_t)(jt * 4) * 32 + lane;
        const uint4* p1 = p0 + 128;
        float dA[2][4] = {}, dB[2][4] = {};
        #pragma unroll
        for (int ks = 0; ks < 4; ks++) {
            uint4 bA = p0[ks * 32];
            uint4 bB = p1[ks * 32];
            #pragma unroll
            for (int mt = 0; mt < 2; mt++) {
                mma16816(dA[mt], ah[mt][ks][0], ah[mt][ks][1], ah[mt][ks][2], ah[mt][ks][3], bA.x, bA.y);
                mma16816(dA[mt], ah[mt][ks][0], ah[mt][ks][1], ah[mt][ks][2], ah[mt][ks][3], bA.z, bA.w);
                mma16816(dA[mt], al[mt][ks][0], al[mt][ks][1], al[mt][ks][2], al[mt][ks][3], bA.x, bA.y);
                mma16816(dB[mt], ah[mt][ks][0], ah[mt][ks][1], ah[mt][ks][2], ah[mt][ks][3], bB.x, bB.y);
                mma16816(dB[mt], ah[mt][ks][0], ah[mt][ks][1], ah[mt][ks][2], ah[mt][ks][3], bB.z, bB.w);
                mma16816(dB[mt], al[mt][ks][0], al[mt][ks][1], al[mt][ks][2], al[mt][ks][3], bB.x, bB.y);
            }
        }
        #pragma unroll
        for (int mt = 0; mt < 2; mt++) {
            int le0 = warp * 32 + mt * 16 + r0;
            tp_acc(jt * 8,     dA[mt], accS[mt], accG[mt], Fs, Ds, rh[mt], le0);
            tp_acc(jt * 8 + 8, dB[mt], accS[mt], accG[mt], Fs, Ds, rh[mt], le0);
        }
    }
}

__device__ __forceinline__ void load_afrags(
        const __nv_bfloat16* Hh, const __nv_bfloat16* Hl,
        unsigned ah[2][4][4], unsigned al[2][4][4],
        int warp, int r0, int c0) {
    #pragma unroll
    for (int mt = 0; mt < 2; mt++) {
        int le0 = warp * 32 + mt * 16 + r0;
        int le1 = le0 + 8;
        #pragma unroll
        for (int ks = 0; ks < 4; ks++) {
            int kb = ks * 16 + c0;
            ah[mt][ks][0] = *(const unsigned*)&Hh[le0 * 66 + kb];
            ah[mt][ks][1] = *(const unsigned*)&Hh[le1 * 66 + kb];
            ah[mt][ks][2] = *(const unsigned*)&Hh[le0 * 66 + kb + 8];
            ah[mt][ks][3] = *(const unsigned*)&Hh[le1 * 66 + kb + 8];
            al[mt][ks][0] = *(const unsigned*)&Hl[le0 * 66 + kb];
            al[mt][ks][1] = *(const unsigned*)&Hl[le1 * 66 + kb];
            al[mt][ks][2] = *(const unsigned*)&Hl[le0 * 66 + kb + 8];
            al[mt][ks][3] = *(const unsigned*)&Hl[le1 * 66 + kb + 8];
        }
    }
}

// ---------------------------------------------------------------------------
// Fused msg pass: 128 edges / block, 128 threads (validated R12).
// ---------------------------------------------------------------------------
__global__ void __launch_bounds__(128) k_msg_mma(
        const float* __restrict__ pos,
        const int* __restrict__ src, const int* __restrict__ dst,
        const float* __restrict__ eattr,
        const float* __restrict__ mw0,
        const uint4* __restrict__ PB,
        int E, int use_b) {
    extern __shared__ char smc[];
    __nv_bfloat16* Hh = (__nv_bfloat16*)smc;
    __nv_bfloat16* Hl = Hh + 128 * 66;
    float* Fs = (float*)(Hl + 128 * 66);
    float* Ds = Fs + 128 * 41;
    float* Rs = Ds + 128 * 8;
    int* Ssrc = (int*)(Rs + 128 * 4);
    int* Sdst = Ssrc + 128;

    const float* node = use_b ? g_nodeB : g_nodeA;
    int t = threadIdx.x;
    int warp = t >> 5, lane = t & 31;
    int ebase = blockIdx.x * 128;

    {
        int eid = ebase + t;
        Ssrc[t] = (eid < E) ? src[eid] : 0;
        Sdst[t] = (eid < E) ? dst[eid] : -1;
    }
    __syncthreads();

    {   // hidden layer
        bool hv = (ebase + t) < E;
        float ea[5];
        #pragma unroll
        for (int a = 0; a < 5; a++)
            ea[a] = hv ? eattr[(size_t)(ebase + t) * 5 + a] : 0.f;
        #pragma unroll
        for (int k = 0; k < 64; k += 2) {
            float s0 = 0.f, s1 = 0.f;
            #pragma unroll
            for (int a = 0; a < 5; a++) {
                s0 += ea[a] * __ldg(&mw0[a * 64 + k]);
                s1 += ea[a] * __ldg(&mw0[a * 64 + k + 1]);
            }
            float h0 = silu_act(s0 * 0.4472135954999579f);
            float h1 = silu_act(s1 * 0.4472135954999579f);
            __nv_bfloat16 h0h = __float2bfloat16(h0);
            __nv_bfloat16 h1h = __float2bfloat16(h1);
            __nv_bfloat16 h0l = __float2bfloat16(h0 - __bfloat162float(h0h));
            __nv_bfloat16 h1l = __float2bfloat16(h1 - __bfloat162float(h1h));
            *(__nv_bfloat162*)&Hh[t * 66 + k] = __nv_bfloat162(h0h, h1h);
            *(__nv_bfloat162*)&Hl[t * 66 + k] = __nv_bfloat162(h0l, h1l);
        }
    }
    for (int idx = t; idx < 5120; idx += 128) {
        int e = idx / 40, c = idx - e * 40;
        Fs[e * 41 + c] = (Sdst[e] >= 0) ? node[(size_t)Ssrc[e] * 40 + c] : 0.f;
    }
    {
        float rx = 0.f, ry = 0.f, rz = 0.f;
        if (Sdst[t] >= 0) {
            const float* ps = pos + Ssrc[t] * 3;
            const float* pd = pos + Sdst[t] * 3;
            rx = pd[0] - ps[0]; ry = pd[1] - ps[1]; rz = pd[2] - ps[2];
            float inv = rsqrtf(rx * rx + ry * ry + rz * rz);
            rx *= inv; ry *= inv; rz *= inv;
        }
        Rs[t * 4] = rx; Rs[t * 4 + 1] = ry; Rs[t * 4 + 2] = rz;
    }
    __syncthreads();

    for (int idx = t; idx < 1024; idx += 128) {
        int e = idx >> 3, u = idx & 7;
        Ds[idx] = Fs[e * 41 + 16 + u * 3]     * Rs[e * 4]
                + Fs[e * 41 + 17 + u * 3]     * Rs[e * 4 + 1]
                + Fs[e * 41 + 18 + u * 3]     * Rs[e * 4 + 2];
    }
    __syncthreads();

    int r0 = lane >> 2;
    int c0 = (lane & 3) * 2;
    unsigned ah[2][4][4], al[2][4][4];
    load_afrags(Hh, Hl, ah, al, warp, r0, c0);
    float rh[2][2][3];
    #pragma unroll
    for (int mt = 0; mt < 2; mt++) {
        int le0 = warp * 32 + mt * 16 + r0;
        #pragma unroll
        for (int i = 0; i < 3; i++) {
            rh[mt][0][i] = Rs[le0 * 4 + i];
            rh[mt][1][i] = Rs[(le0 + 8) * 4 + i];
        }
    }

    float accS[2][2][4] = {};
    float accG[2][2][2][3] = {};
    mma_tp_loop(PB, ah, al, accS, accG, Fs, Ds, rh, warp, r0, lane);

    #pragma unroll
    for (int mt = 0; mt < 2; mt++) {
        #pragma unroll
        for (int ei = 0; ei < 2; ei++) {
            int le = warp * 32 + mt * 16 + r0 + ei * 8;
            int dN = Sdst[le];
            if (dN < 0) continue;
            float* mp = g_msgs + (size_t)dN * 40;
            atomicAdd(mp + c0,     PW0_8 * accS[mt][ei][0]);
            atomicAdd(mp + c0 + 1, PW0_8 * accS[mt][ei][1]);
            atomicAdd(mp + c0 + 8, PW0_8 * accS[mt][ei][2]);
            atomicAdd(mp + c0 + 9, PW0_8 * accS[mt][ei][3]);
            #pragma unroll
            for (int ci = 0; ci < 2; ci++) {
                int wv = c0 + ci;
                #pragma unroll
                for (int i = 0; i < 3; i++)
                    atomicAdd(mp + 16 + wv * 3 + i, PW0_8 * accG[mt][ei][ci][i]);
            }
        }
    }
}

// ---------------------------------------------------------------------------
// Fused lig pass: 128 inter-edges / block, 128 threads. TP result in smem,
// Z (bf16 hi/lo) written in-block. A = Hl from g_Hlh/g_Hll.
// ---------------------------------------------------------------------------
__global__ void __launch_bounds__(128) k_lig_mma(
        const int* __restrict__ irec, const int* __restrict__ ilig,
        const uint4* __restrict__ PB, int EI) {
    extern __shared__ char smc[];
    __nv_bfloat16* Hh = (__nv_bfloat16*)smc;            // 128*66
    __nv_bfloat16* Hl = Hh + 128 * 66;                  // 128*66
    float* Fs = (float*)(Hl + 128 * 66);                // 128*41 (lig features)
    float* Fr = Fs + 128 * 41;                          // 128*41 (rec features)
    float* Os = Fr + 128 * 41;                          // 128*41 (TP out)
    float* Ds = Os + 128 * 41;                          // 128*8
    float* Rs = Ds + 128 * 8;                           // 128*4
    int* Sil = (int*)(Rs + 128 * 4);
    int* Sir = Sil + 128;

    int t = threadIdx.x;
    int warp = t >> 5, lane = t & 31;
    int ebase = blockIdx.x * 128;
    int nval = min(128, EI - ebase);

    {
        int eid = ebase + t;
        Sil[t] = (t < nval) ? ilig[eid] : -1;
        Sir[t] = (t < nval) ? irec[eid] : 0;
    }
    __syncthreads();

    for (int idx = t; idx < 128 * 32; idx += 128) {     // Hh/Hl from global
        int e = idx >> 5, k2 = (idx & 31) * 2;
        __nv_bfloat162 vh(__float2bfloat16(0.f), __float2bfloat16(0.f));
        __nv_bfloat162 vl = vh;
        if (e < nval) {
            vh = *(const __nv_bfloat162*)&g_Hlh[(size_t)(ebase + e) * 64 + k2];
            vl = *(const __nv_bfloat162*)&g_Hll[(size_t)(ebase + e) * 64 + k2];
        }
        *(__nv_bfloat162*)&Hh[e * 66 + k2] = vh;
        *(__nv_bfloat162*)&Hl[e * 66 + k2] = vl;
    }
    for (int idx = t; idx < 5120; idx += 128) {
        int e = idx / 40, c = idx - e * 40;
        float vl = 0.f, vr = 0.f;
        if (Sil[e] >= 0) {
            vl = g_nodeA[(size_t)Sil[e] * 40 + c];
            vr = g_nodeA[(size_t)Sir[e] * 40 + c];
        }
        Fs[e * 41 + c] = vl;
        Fr[e * 41 + c] = vr;
    }
    {
        float rx = 0.f, ry = 0.f, rz = 0.f;
        if (t < nval) {
            rx = g_rh[(ebase + t) * 3];
            ry = g_rh[(ebase + t) * 3 + 1];
            rz = g_rh[(ebase + t) * 3 + 2];
        }
        Rs[t * 4] = rx; Rs[t * 4 + 1] = ry; Rs[t * 4 + 2] = rz;
    }
    __syncthreads();

    for (int idx = t; idx < 1024; idx += 128) {
        int e = idx >> 3, u = idx & 7;
        Ds[idx] = Fs[e * 41 + 16 + u * 3]     * Rs[e * 4]
                + Fs[e * 41 + 17 + u * 3]     * Rs[e * 4 + 1]
                + Fs[e * 41 + 18 + u * 3]     * Rs[e * 4 + 2];
    }
    __syncthreads();

    int r0 = lane >> 2;
    int c0 = (lane & 3) * 2;
    unsigned ah[2][4][4], al[2][4][4];
    load_afrags(Hh, Hl, ah, al, warp, r0, c0);
    float rh[2][2][3];
    #pragma unroll
    for (int mt = 0; mt < 2; mt++) {
        int le0 = warp * 32 + mt * 16 + r0;
        #pragma unroll
        for (int i = 0; i < 3; i++) {
            rh[mt][0][i] = Rs[le0 * 4 + i];
            rh[mt][1][i] = Rs[(le0 + 8) * 4 + i];
        }
    }

    float accS[2][2][4] = {};
    float accG[2][2][2][3] = {};
    mma_tp_loop(PB, ah, al, accS, accG, Fs, Ds, rh, warp, r0, lane);

    // write TP result (lig_emb) to smem
    #pragma unroll
    for (int mt = 0; mt < 2; mt++) {
        #pragma unroll
        for (int ei = 0; ei < 2; ei++) {
            int le = warp * 32 + mt * 16 + r0 + ei * 8;
            float* op = Os + le * 41;
            op[c0]     = PW0_8 * accS[mt][ei][0];
            op[c0 + 1] = PW0_8 * accS[mt][ei][1];
            op[c0 + 8] = PW0_8 * accS[mt][ei][2];
            op[c0 + 9] = PW0_8 * accS[mt][ei][3];
            #pragma unroll
            for (int ci = 0; ci < 2; ci++) {
                int wv = c0 + ci;
                #pragma unroll
                for (int i = 0; i < 3; i++)
                    op[16 + wv * 3 + i] = PW0_8 * accG[mt][ei][ci][i];
            }
        }
    }
    __syncthreads();

    // Z = outer(lig_emb, fr) (scalar block) + vec-dot block, bf16 hi/lo
    for (int idx = t; idx < nval * 320; idx += 128) {
        int e = idx / 320, p = idx - e * 320;
        float z;
        if (p < 256) {
            z = Os[e * 41 + (p >> 4)] * Fr[e * 41 + (p & 15)];
        } else {
            int q = p - 256; int u = q >> 3, v = q & 7;
            z = (Os[e * 41 + 16 + u * 3] * Fr[e * 41 + 16 + v * 3]
               + Os[e * 41 + 17 + u * 3] * Fr[e * 41 + 17 + v * 3]
               + Os[e * 41 + 18 + u * 3] * Fr[e * 41 + 18 + v * 3]) * INV_SQ3;
        }
        __nv_bfloat16 zh = __float2bfloat16(z);
        g_Zh[(size_t)(ebase + e) * 320 + p] = zh;
        g_Zl[(size_t)(ebase + e) * 320 + p] = __float2bfloat16(z - __bfloat162float(zh));
    }
}

// ---------------------------------------------------------------------------
// Rec GEMM fused with output contraction (validated R12).
// ---------------------------------------------------------------------------
__global__ void __launch_bounds__(256) k_mma_rec(
        const __nv_bfloat16* __restrict__ Ah, const __nv_bfloat16* __restrict__ Al,
        const __nv_bfloat16* __restrict__ Bh, const __nv_bfloat16* __restrict__ Bl,
        float* __restrict__ outp, int M) {
    const int N = 512, K = 320;
    extern __shared__ char smx[];
    unsigned sbase = (unsigned)__cvta_generic_to_shared(smx);
    int t = threadIdx.x;
    int warp = t >> 5, lane = t & 31;
    int wm = warp >> 1, wn = warp & 1;
    int rowBase = blockIdx.y * 128;
    int nBase   = blockIdx.x * 128;
    int nIter = K >> 5;

    {
        #pragma unroll
        for (int i = 0; i < 2; i++) {
            int c = t + i * 256;
            int row = c >> 2, ch = c & 3;
            int br = min(nBase + row, N - 1);
            unsigned d = sbase + row * 80 + ch * 16;
            cpa16(d,         Ah + (size_t)(rowBase + row) * K + ch * 8);
            cpa16(d + 10240, Al + (size_t)(rowBase + row) * K + ch * 8);
            cpa16(d + 20480, Bh + (size_t)br * K + ch * 8);
            cpa16(d + 30720, Bl + (size_t)br * K + ch * 8);
        }
        cpa_commit();
    }

    float d[2][8][4];
    #pragma unroll
    for (int mi = 0; mi < 2; mi++)
        #pragma unroll
        for (int ni = 0; ni < 8; ni++)
            #pragma unroll
            for (int q = 0; q < 4; q++) d[mi][ni][q] = 0.f;

    for (int it = 0; it < nIter; it++) {
        cpa_wait0();
        __syncthreads();
        if (it + 1 < nIter) {
            int k0 = (it + 1) * 32;
            unsigned sb = sbase + ((it + 1) & 1) * 40960;
            #pragma unroll
            for (int i = 0; i < 2; i++) {
                int c = t + i * 256;
                int row = c >> 2, ch = c & 3;
                int br = min(nBase + row, N - 1);
                unsigned dd = sb + row * 80 + ch * 16;
                cpa16(dd,         Ah + (size_t)(rowBase + row) * K + k0 + ch * 8);
                cpa16(dd + 10240, Al + (size_t)(rowBase + row) * K + k0 + ch * 8);
                cpa16(dd + 20480, Bh + (size_t)br * K + k0 + ch * 8);
                cpa16(dd + 30720, Bl + (size_t)br * K + k0 + ch * 8);
            }
            cpa_commit();
        }
        unsigned ab = sbase + (it & 1) * 40960;
        unsigned bb = ab + 20480;
        #pragma unroll
        for (int ks = 0; ks < 2; ks++) {
            unsigned ka = ab + ks * 32 + (lane & 3) * 4;
            unsigned kb = bb + ks * 32 + (lane & 3) * 4;
            unsigned ah[2][4], al[2][4];
            #pragma unroll
            for (int mi = 0; mi < 2; mi++) {
                unsigned rb = (unsigned)((wm * 32 + mi * 16 + (lane >> 2)) * 80);
                ah[mi][0] = lds32(ka + rb);
                ah[mi][1] = lds32(ka + rb + 8 * 80);
                ah[mi][2] = lds32(ka + rb + 16);
                ah[mi][3] = lds32(ka + rb + 8 * 80 + 16);
                al[mi][0] = lds32(ka + rb + 10240);
                al[mi][1] = lds32(ka + rb + 8 * 80 + 10240);
                al[mi][2] = lds32(ka + rb + 16 + 10240);
                al[mi][3] = lds32(ka + rb + 8 * 80 + 16 + 10240);
            }
            #pragma unroll
            for (int ni = 0; ni < 8; ni++) {
                unsigned nb = (unsigned)((wn * 64 + ni * 8 + (lane >> 2)) * 80);
                unsigned bh0 = lds32(kb + nb);
                unsigned bh1 = lds32(kb + nb + 16);
                unsigned bl0 = lds32(kb + nb + 10240);
                unsigned bl1 = lds32(kb + nb + 16 + 10240);
                #pragma unroll
                for (int mi = 0; mi < 2; mi++) {
                    mma16816(d[mi][ni], ah[mi][0], ah[mi][1], ah[mi][2], ah[mi][3], bh0, bh1);
                    mma16816(d[mi][ni], ah[mi][0], ah[mi][1], ah[mi][2], ah[mi][3], bl0, bl1);
                    mma16816(d[mi][ni], al[mi][0], al[mi][1], al[mi][2], al[mi][3], bh0, bh1);
                }
            }
        }
        __syncthreads();
    }

    int kb0 = (nBase >> 3) + wn * 8;
    int w0 = (lane & 3) * 2;
    #pragma unroll
    for (int mi = 0; mi < 2; mi++) {
        int r0 = rowBase + wm * 32 + mi * 16 + (lane >> 2);
        int r1 = r0 + 8;
        float a00 = 0.f, a01 = 0.f, a10 = 0.f, a11 = 0.f;
        #pragma unroll
        for (int ni = 0; ni < 8; ni++) {
            int k = kb0 + ni;
            float h0 = (r0 < M) ? g_Hr[r0 * 64 + k] : 0.f;
            float h1 = (r1 < M) ? g_Hr[r1 * 64 + k] : 0.f;
            a00 += h0 * d[mi][ni][0]; a01 += h0 * d[mi][ni][1];
            a10 += h1 * d[mi][ni][2]; a11 += h1 * d[mi][ni][3];
        }
        if (r0 < M) {
            atomicAdd(outp + r0 * 8 + w0,     PWREC_8 * a00);
            atomicAdd(outp + r0 * 8 + w0 + 1, PWREC_8 * a01);
        }
        if (r1 < M) {
            atomicAdd(outp + r1 * 8 + w0,     PWREC_8 * a10);
            atomicAdd(outp + r1 * 8 + w0 + 1, PWREC_8 * a11);
        }
    }
}

// ---------------------------------------------------------------------------
// Node embedding MLP + zero geo + zero msgs.
// ---------------------------------------------------------------------------
__global__ void k_embed(const float* __restrict__ x,
                        const float* __restrict__ w0,
                        const float* __restrict__ w1,
                        int N) {
    __shared__ float sh[8][64];
    int warp = threadIdx.x >> 5, lane = threadIdx.x & 31;
    int n = blockIdx.x * 8 + warp;
    if (n >= N) return;
    float xa[10];
    #pragma unroll
    for (int a = 0; a < 10; a++) xa[a] = x[n * 10 + a];
    #pragma unroll
    for (int r = 0; r < 2; r++) {
        int k = lane + r * 32;
        float s = 0.f;
        #pragma unroll
        for (int a = 0; a < 10; a++) s += xa[a] * w0[a * 64 + k];
        sh[warp][k] = silu_act(s * 0.31622776601683794f);
    }
    __syncwarp();
    if (lane < 16) {
        float s = 0.f;
        #pragma unroll
        for (int k = 0; k < 64; k++) s += sh[warp][k] * w1[k * 16 + lane];
        g_nodeA[n * 40 + lane] = s * 0.125f;
    }
    if (lane < 24) g_nodeA[n * 40 + 16 + lane] = 0.f;
    g_msgs[n * 40 + lane] = 0.f;
    if (lane < 8) g_msgs[n * 40 + 32 + lane] = 0.f;
}

// ---------------------------------------------------------------------------
// Update step. Re-zeroes g_msgs.
// ---------------------------------------------------------------------------
__global__ void k_upd(const float* __restrict__ uw0,
                      const float* __restrict__ uw1,
                      const float* __restrict__ imp,
                      int N, float degInv, int step) {
    __shared__ float cat[8][32];
    __shared__ float hh[8][64];
    int warp = threadIdx.x >> 5, lane = threadIdx.x & 31;
    int n = blockIdx.x * 8 + warp;
    if (n >= N) return;
    const float* in = step ? g_nodeB : g_nodeA;
    float* out = step ? g_nodeA : g_nodeB;
    float sc = imp[0] * degInv;
    float gscale = step ? 0.5f : 1.0f;
    if (lane < 16) {
        cat[warp][lane]      = g_msgs[n * 40 + lane] * sc;
        cat[warp][16 + lane] = in[n * 40 + lane];
    }
    __syncwarp();
    #pragma unroll
    for (int r = 0; r < 2; r++) {
        int k = lane + r * 32;
        float s = 0.f;
        #pragma unroll
        for (int a = 0; a < 32; a++) s += cat[warp][a] * uw0[a * 64 + k];
        hh[warp][k] = silu_act(s * 0.17677669529663687f);
    }
    __syncwarp();
    if (lane < 16) {
        float s = 0.f;
        #pragma unroll
        for (int k = 0; k < 64; k++) s += hh[warp][k] * uw1[k * 16 + lane];
        out[n * 40 + lane] = s * 0.125f;
    }
    if (lane < 24)
        out[n * 40 + 16 + lane] =
            (g_msgs[n * 40 + 16 + lane] * sc + in[n * 40 + 16 + lane]) * gscale;
    g_msgs[n * 40 + lane] = 0.f;
    if (lane < 8) g_msgs[n * 40 + 32 + lane] = 0.f;
}

// ---------------------------------------------------------------------------
// Inter-edge prep: rhat + dist-embed -> Hl (bf16 hi/lo), Hr (fp32).
// ---------------------------------------------------------------------------
__global__ void k_prep(const float* __restrict__ pos,
                       const int* __restrict__ irec, const int* __restrict__ ilig,
                       const float* __restrict__ lw0,
                       const float* __restrict__ rw0,
                       int EI) {
    int idx = blockIdx.x * 256 + threadIdx.x;
    int e = idx >> 6, k = idx & 63;
    if (e >= EI) return;
    int ir = irec[e], il = ilig[e];
    float rx = pos[il * 3]     - pos[ir * 3];
    float ry = pos[il * 3 + 1] - pos[ir * 3 + 1];
    float rz = pos[il * 3 + 2] - pos[ir * 3 + 2];
    float d = sqrtf(rx * rx + ry * ry + rz * rz);
    float inv = 1.f / d;
    if (k == 0) {
        g_rh[e * 3]     = rx * inv;
        g_rh[e * 3 + 1] = ry * inv;
        g_rh[e * 3 + 2] = rz * inv;
    }
    float s1 = 0.f, s2 = 0.f;
    #pragma unroll
    for (int a = 0; a < 20; a++) {
        float diff = d * (21.f / 5.f) - (float)(a + 1);
        float t1 = diff + 1.f, t2 = 1.f - diff;
        float v = 0.f;
        if (t1 > 0.f && t2 > 0.f) v = DEMB_C * expf(-1.f / t1 - 1.f / t2);
        s1 += v * lw0[a * 64 + k];
        s2 += v * rw0[a * 64 + k];
    }
    float hl = silu_act(s1 * 0.22360679774997896f);
    __nv_bfloat16 hh = __float2bfloat16(hl);
    g_Hlh[idx] = hh;
    g_Hll[idx] = __float2bfloat16(hl - __bfloat162float(hh));
    g_Hr[idx] = silu_act(s2 * 0.22360679774997896f);
}

// ---------------------------------------------------------------------------
extern "C" void kernel_launch(void* const* d_in, const int* in_sizes, int n_in,
                              void* d_out, int out_size) {
    const float* x     = (const float*)d_in[0];
    const float* pos   = (const float*)d_in[1];
    const int*   eidx  = (const int*)  d_in[2];
    const float* eattr = (const float*)d_in[3];
    const int*   iidx  = (const int*)  d_in[4];
    const float* emb_w0= (const float*)d_in[5];
    const float* emb_w1= (const float*)d_in[6];
    const float* imp0  = (const float*)d_in[7];
    const float* m0w0  = (const float*)d_in[8];
    const float* m0w1  = (const float*)d_in[9];
    const float* u0w0  = (const float*)d_in[10];
    const float* u0w1  = (const float*)d_in[11];
    const float* imp1  = (const float*)d_in[12];
    const float* m1w0  = (const float*)d_in[13];
    const float* m1w1  = (const float*)d_in[14];
    const float* u1w0  = (const float*)d_in[15];
    const float* u1w1  = (const float*)d_in[16];
    const float* lw0   = (const float*)d_in[17];
    const float* lw1   = (const float*)d_in[18];
    const float* rw0   = (const float*)d_in[19];
    const float* rw1   = (const float*)d_in[20];
    float* outp = (float*)d_out;

    int N  = in_sizes[0] / 10;
    int E  = in_sizes[2] / 2;
    int EI = in_sizes[4] / 2;
    float degInv = (float)(1.0 / sqrt((double)E / (double)N));

    uint4 *pPB;
    __nv_bfloat16 *pTWh, *pTWl, *pZh, *pZl;
    cudaGetSymbolAddress((void**)&pPB,  g_PB);
    cudaGetSymbolAddress((void**)&pTWh, g_TWth);
    cudaGetSymbolAddress((void**)&pTWl, g_TWtl);
    cudaGetSymbolAddress((void**)&pZh,  g_Zh);
    cudaGetSymbolAddress((void**)&pZl,  g_Zl);

    const int SM_MMA = 81920;
    const int SM_MSG = 2 * 128 * 66 * 2 + 128 * 41 * 4 + 128 * 8 * 4
                     + 128 * 4 * 4 + 128 * 8;                   // 61952
    const int SM_LIG = 2 * 128 * 66 * 2 + 3 * 128 * 41 * 4 + 128 * 8 * 4
                     + 128 * 4 * 4 + 128 * 8;                   // 103936
    cudaFuncSetAttribute(k_mma_rec, cudaFuncAttributeMaxDynamicSharedMemorySize, SM_MMA);
    cudaFuncSetAttribute(k_msg_mma, cudaFuncAttributeMaxDynamicSharedMemorySize, SM_MSG);
    cudaFuncSetAttribute(k_lig_mma, cudaFuncAttributeMaxDynamicSharedMemorySize, SM_LIG);

    k_prepPB<<<(72 * 4 * 32 + 255) / 256, 256>>>(m0w1, 0);
    k_prepPB<<<(72 * 4 * 32 + 255) / 256, 256>>>(m1w1, 1);
    k_prepPB<<<(72 * 4 * 32 + 255) / 256, 256>>>(lw1, 2);
    k_prepTW<<<(512 * 320 + 255) / 256, 256>>>(rw1);
    k_zero<<<(EI * 8 + 255) / 256, 256>>>(outp, EI * 8);
    k_embed<<<(N + 7) / 8, 256>>>(x, emb_w0, emb_w1, N);

    int gE = (E + 127) / 128;
    k_msg_mma<<<gE, 128, SM_MSG>>>(pos, eidx, eidx + E, eattr, m0w0, pPB, E, 0);
    k_upd<<<(N + 7) / 8, 256>>>(u0w0, u0w1, imp0, N, degInv, 0);
    k_msg_mma<<<gE, 128, SM_MSG>>>(pos, eidx, eidx + E, eattr, m1w0,
                                   pPB + 72 * 4 * 32, E, 1);
    k_upd<<<(N + 7) / 8, 256>>>(u1w0, u1w1, imp1, N, degInv, 1);

    k_prep<<<(EI * 64 + 255) / 256, 256>>>(pos, iidx, iidx + EI, lw0, rw0, EI);
    int gI = (EI + 127) / 128;
    k_lig_mma<<<gI, 128, SM_LIG>>>(iidx, iidx + EI, pPB + 2 * 72 * 4 * 32, EI);
    dim3 gM(4, (EI + 127) / 128);
    k_mma_rec<<<gM, 256, SM_MMA>>>(pZh, pZl, pTWh, pTWl, outp, EI);
}